// round 1
// baseline (speedup 1.0000x reference)
#include <cuda_runtime.h>
#include <math.h>

#define S_TOK 4096
#define DE 256
#define DC 64
#define DIN 320
#define DM 64
#define DEPTH 4
#define DTs 0.1f
#define SCALE 0.0625f   /* 1/sqrt(256) */
#define KSPLIT 2

/* output layout offsets (flattened concat of the reference tuple, float32) */
#define E_OFF  (S_TOK*DE)            /* 1048576 */
#define P_OFF  (E_OFF + S_TOK)
#define G_OFF  (P_OFF + S_TOK)
#define M_OFF  (G_OFF + S_TOK)       /* 1060864 */
#define C_OFF  (M_OFF + S_TOK*DM)    /* 1323008 */
#define L_OFF  (C_OFF + S_TOK*DM)    /* 1585152 */
#define A_OFF  (L_OFF + S_TOK)       /* 1589248 */
#define D_OFF  (A_OFF + S_TOK)       /* 1593344 */

/* persistent state (device globals: no allocation allowed) */
__device__ float g_e[S_TOK*DE];
__device__ float g_q[S_TOK*DE];
__device__ float g_k[S_TOK*DE];
__device__ float g_v[S_TOK*DE];
__device__ float g_m[S_TOK*DM];      /* raw m */
__device__ float g_mt[S_TOK*DM];     /* m~ = l*m (combined membrane*lifespan mask) */
__device__ float g_E[S_TOK];
__device__ float g_P[S_TOK];
__device__ float g_G[S_TOK];
__device__ float g_l[S_TOK];
__device__ float g_hpart[KSPLIT][S_TOK*DE];
__device__ float g_Mpart[KSPLIT][S_TOK];
__device__ float g_Lpart[KSPLIT][S_TOK];
__device__ int   g_alive_count;

/* ------------------------------------------------------------------ init */
__global__ void init_kernel(const float* __restrict__ e, const float* __restrict__ Ein,
                            const float* __restrict__ Pin, const float* __restrict__ Gin,
                            const float* __restrict__ min_, const float* __restrict__ lin)
{
    int i = blockIdx.x * 256 + threadIdx.x;      /* grid covers S_TOK*DE exactly */
    g_e[i] = e[i];
    if (i < S_TOK*DM) {
        float mv = min_[i];
        g_m[i]  = mv;
        g_mt[i] = mv * lin[i / DM];
    }
    if (i < S_TOK) {
        g_l[i] = lin[i]; g_E[i] = Ein[i]; g_P[i] = Pin[i]; g_G[i] = Gin[i];
    }
    if (i == 0) g_alive_count = 0;
}

/* ------------------------------------------------------- QKV projections */
/* out = [e|c] @ W + b ; M=4096 K=320 N=256 ; block 64x64, 256 thr, 4x4 micro */
__global__ void __launch_bounds__(256) qkv_kernel(
    const float* __restrict__ cin,
    const float* __restrict__ wq, const float* __restrict__ bq,
    const float* __restrict__ wk, const float* __restrict__ bk,
    const float* __restrict__ wv, const float* __restrict__ bv, int layer)
{
    __shared__ float sA[16][68];   /* x tile transposed [k][m], padded */
    __shared__ float sB[16][64];   /* W tile [k][n] */
    const int tid = threadIdx.x;
    const int m0 = blockIdx.x * 64, n0 = blockIdx.y * 64;
    const int which = blockIdx.z;
    const float* W = (which == 0 ? wq : which == 1 ? wk : wv) + (size_t)layer * DIN * DE;
    const float* B = (which == 0 ? bq : which == 1 ? bk : bv) + layer * DE;
    float* out = (which == 0 ? g_q : which == 1 ? g_k : g_v);
    const int ty = tid >> 4, tx = tid & 15;

    float acc[4][4] = {};
    for (int kt = 0; kt < 20; kt++) {
        const int k0 = kt * 16;
        __syncthreads();
        for (int idx = tid; idx < 1024; idx += 256) {
            int mm = idx >> 4, kk = idx & 15;
            float v;
            if (k0 < 256) v = g_e[(m0 + mm) * DE + k0 + kk];
            else          v = cin[(m0 + mm) * DC + (k0 - 256) + kk];
            sA[kk][mm] = v;
        }
        for (int idx = tid; idx < 1024; idx += 256) {
            int kk = idx >> 6, nn = idx & 63;
            sB[kk][nn] = W[(size_t)(k0 + kk) * DE + n0 + nn];
        }
        __syncthreads();
        #pragma unroll
        for (int kk = 0; kk < 16; kk++) {
            float4 a = *(const float4*)&sA[kk][4 * ty];
            float4 b = *(const float4*)&sB[kk][4 * tx];
            acc[0][0] += a.x*b.x; acc[0][1] += a.x*b.y; acc[0][2] += a.x*b.z; acc[0][3] += a.x*b.w;
            acc[1][0] += a.y*b.x; acc[1][1] += a.y*b.y; acc[1][2] += a.y*b.z; acc[1][3] += a.y*b.w;
            acc[2][0] += a.z*b.x; acc[2][1] += a.z*b.y; acc[2][2] += a.z*b.z; acc[2][3] += a.z*b.w;
            acc[3][0] += a.w*b.x; acc[3][1] += a.w*b.y; acc[3][2] += a.w*b.z; acc[3][3] += a.w*b.w;
        }
    }
    #pragma unroll
    for (int i = 0; i < 4; i++) {
        float4 r;
        r.x = acc[i][0] + B[n0 + 4*tx + 0];
        r.y = acc[i][1] + B[n0 + 4*tx + 1];
        r.z = acc[i][2] + B[n0 + 4*tx + 2];
        r.w = acc[i][3] + B[n0 + 4*tx + 3];
        *(float4*)(out + (size_t)(m0 + 4*ty + i) * DE + n0 + 4*tx) = r;
    }
}

/* ----------------------------------------------------- fused attention */
/* BM=64 queries x (S/KSPLIT) keys, online softmax, unnormalized partials. */
#define ATTN_SMEM_FLOATS (64*260 + 64*260 + 64*128 + 64*68 + 64*68 + 64*64)
#define ATTN_SMEM_BYTES  (ATTN_SMEM_FLOATS * 4)

__global__ void __launch_bounds__(256, 1) attn_kernel()
{
    extern __shared__ float sm[];
    float* sQ  = sm;                 /* [64][260] q tile, row-major padded   */
    float* sK  = sQ  + 64*260;       /* [64][260] k tile                     */
    float* sV  = sK  + 64*260;       /* [64][128] v half-tile                */
    float* sMq = sV  + 64*128;       /* [64][68]  m~ query tile              */
    float* sMk = sMq + 64*68;        /* [64][68]  m~ key tile                */
    float* sP  = sMk + 64*68;        /* [64][64]  scores / probabilities     */

    const int tid  = threadIdx.x;
    const int row0 = blockIdx.x * 64;
    const int ks   = blockIdx.y;
    const int key_base = ks * (S_TOK / KSPLIT);
    const int g = tid >> 5, lane = tid & 31;
    const int ty = tid >> 4, tx = tid & 15;

    for (int idx = tid; idx < 64*64; idx += 256) {
        int r = idx >> 6, d4 = (idx & 63) << 2;
        *(float4*)(sQ + r*260 + d4) = *(const float4*)(g_q + (size_t)(row0 + r)*DE + d4);
    }
    for (int idx = tid; idx < 64*16; idx += 256) {
        int r = idx >> 4, d4 = (idx & 15) << 2;
        *(float4*)(sMq + r*68 + d4) = *(const float4*)(g_mt + (size_t)(row0 + r)*DM + d4);
    }

    float acc[8][8];
    #pragma unroll
    for (int i = 0; i < 8; i++)
        #pragma unroll
        for (int j = 0; j < 8; j++) acc[i][j] = 0.f;
    float rowM[8], rowL[8];
    #pragma unroll
    for (int i = 0; i < 8; i++) { rowM[i] = -INFINITY; rowL[i] = 0.f; }

    for (int kt = 0; kt < (S_TOK / KSPLIT) / 64; kt++) {
        const int key0 = key_base + kt * 64;
        __syncthreads();
        for (int idx = tid; idx < 64*64; idx += 256) {
            int r = idx >> 6, d4 = (idx & 63) << 2;
            *(float4*)(sK + r*260 + d4) = *(const float4*)(g_k + (size_t)(key0 + r)*DE + d4);
        }
        for (int idx = tid; idx < 64*16; idx += 256) {
            int r = idx >> 4, d4 = (idx & 15) << 2;
            *(float4*)(sMk + r*68 + d4) = *(const float4*)(g_mt + (size_t)(key0 + r)*DM + d4);
        }
        for (int idx = tid; idx < 64*32; idx += 256) {
            int r = idx >> 5, d4 = (idx & 31) << 2;
            *(float4*)(sV + r*128 + d4) = *(const float4*)(g_v + (size_t)(key0 + r)*DE + d4);
        }
        __syncthreads();

        /* score phase: q.k over 256 dims, m~.m~ over 64 dims */
        float sqk[4][4] = {}; float smm[4][4] = {};
        {
            const float* qp = sQ + 4*ty*260;
            #pragma unroll 4
            for (int d = 0; d < DE; d += 4) {
                float4 qa[4], kb[4];
                #pragma unroll
                for (int i = 0; i < 4; i++) qa[i] = *(const float4*)(qp + i*260 + d);
                #pragma unroll
                for (int j = 0; j < 4; j++) kb[j] = *(const float4*)(sK + (tx + 16*j)*260 + d);
                #pragma unroll
                for (int i = 0; i < 4; i++)
                    #pragma unroll
                    for (int j = 0; j < 4; j++)
                        sqk[i][j] += qa[i].x*kb[j].x + qa[i].y*kb[j].y
                                   + qa[i].z*kb[j].z + qa[i].w*kb[j].w;
            }
            const float* mp = sMq + 4*ty*68;
            #pragma unroll 4
            for (int d = 0; d < DM; d += 4) {
                float4 qa[4], kb[4];
                #pragma unroll
                for (int i = 0; i < 4; i++) qa[i] = *(const float4*)(mp + i*68 + d);
                #pragma unroll
                for (int j = 0; j < 4; j++) kb[j] = *(const float4*)(sMk + (tx + 16*j)*68 + d);
                #pragma unroll
                for (int i = 0; i < 4; i++)
                    #pragma unroll
                    for (int j = 0; j < 4; j++)
                        smm[i][j] += qa[i].x*kb[j].x + qa[i].y*kb[j].y
                                   + qa[i].z*kb[j].z + qa[i].w*kb[j].w;
            }
        }
        #pragma unroll
        for (int i = 0; i < 4; i++)
            #pragma unroll
            for (int j = 0; j < 4; j++)
                sP[(4*ty + i)*64 + tx + 16*j] = sqk[i][j] * SCALE * smm[i][j];
        __syncthreads();

        /* online softmax: warp g owns rows 8g..8g+7 */
        #pragma unroll
        for (int i = 0; i < 8; i++) {
            const int r = 8*g + i;
            float s0 = sP[r*64 + lane];
            float s1 = sP[r*64 + 32 + lane];
            float tmax = fmaxf(s0, s1);
            #pragma unroll
            for (int off = 16; off; off >>= 1)
                tmax = fmaxf(tmax, __shfl_xor_sync(0xffffffffu, tmax, off));
            float newM = fmaxf(rowM[i], tmax);
            float p0 = __expf(s0 - newM);
            float p1 = __expf(s1 - newM);
            float corr = __expf(rowM[i] - newM);
            float ts = p0 + p1;
            #pragma unroll
            for (int off = 16; off; off >>= 1)
                ts += __shfl_xor_sync(0xffffffffu, ts, off);
            rowL[i] = rowL[i] * corr + ts;
            rowM[i] = newM;
            sP[r*64 + lane] = p0;
            sP[r*64 + 32 + lane] = p1;
            #pragma unroll
            for (int jj = 0; jj < 8; jj++) acc[i][jj] *= corr;
        }
        /* no sync needed: each warp reads only its own sP rows below */

        /* AV half 0 (cols 0..127) */
        #pragma unroll 2
        for (int t = 0; t < 64; t += 4) {
            float4 pv[8];
            #pragma unroll
            for (int i = 0; i < 8; i++) pv[i] = *(const float4*)(sP + (8*g + i)*64 + t);
            #pragma unroll
            for (int tt = 0; tt < 4; tt++) {
                float4 vv = *(const float4*)(sV + (t + tt)*128 + 4*lane);
                #pragma unroll
                for (int i = 0; i < 8; i++) {
                    float p = (tt == 0) ? pv[i].x : (tt == 1) ? pv[i].y : (tt == 2) ? pv[i].z : pv[i].w;
                    acc[i][0] += p*vv.x; acc[i][1] += p*vv.y;
                    acc[i][2] += p*vv.z; acc[i][3] += p*vv.w;
                }
            }
        }
        __syncthreads();
        for (int idx = tid; idx < 64*32; idx += 256) {
            int r = idx >> 5, d4 = (idx & 31) << 2;
            *(float4*)(sV + r*128 + d4) = *(const float4*)(g_v + (size_t)(key0 + r)*DE + 128 + d4);
        }
        __syncthreads();
        /* AV half 1 (cols 128..255) */
        #pragma unroll 2
        for (int t = 0; t < 64; t += 4) {
            float4 pv[8];
            #pragma unroll
            for (int i = 0; i < 8; i++) pv[i] = *(const float4*)(sP + (8*g + i)*64 + t);
            #pragma unroll
            for (int tt = 0; tt < 4; tt++) {
                float4 vv = *(const float4*)(sV + (t + tt)*128 + 4*lane);
                #pragma unroll
                for (int i = 0; i < 8; i++) {
                    float p = (tt == 0) ? pv[i].x : (tt == 1) ? pv[i].y : (tt == 2) ? pv[i].z : pv[i].w;
                    acc[i][4] += p*vv.x; acc[i][5] += p*vv.y;
                    acc[i][6] += p*vv.z; acc[i][7] += p*vv.w;
                }
            }
        }
    }

    /* write unnormalized partials + (M, L) */
    #pragma unroll
    for (int i = 0; i < 8; i++) {
        const int row = row0 + 8*g + i;
        float* hp = &g_hpart[ks][(size_t)row * DE];
        *(float4*)(hp + 4*lane)       = make_float4(acc[i][0], acc[i][1], acc[i][2], acc[i][3]);
        *(float4*)(hp + 128 + 4*lane) = make_float4(acc[i][4], acc[i][5], acc[i][6], acc[i][7]);
    }
    #pragma unroll
    for (int i = 0; i < 8; i++) {
        if (lane == i) {
            g_Mpart[ks][row0 + 8*g + i] = rowM[i];
            g_Lpart[ks][row0 + 8*g + i] = rowL[i];
        }
    }
}

/* ----------------------------------------- combine splits + ODE update */
__global__ void combine_kernel(const float* __restrict__ alpha, const float* __restrict__ beta,
                               const float* __restrict__ gamma, const float* __restrict__ basal,
                               int layer)
{
    const int s = blockIdx.x, tid = threadIdx.x;
    const float M0 = g_Mpart[0][s], M1 = g_Mpart[1][s];
    const float L0 = g_Lpart[0][s], L1 = g_Lpart[1][s];
    const float M  = fmaxf(M0, M1);
    const float c0 = __expf(M0 - M), c1 = __expf(M1 - M);
    const float invL = 1.0f / (L0 * c0 + L1 * c1);
    const float h = (g_hpart[0][(size_t)s*DE + tid] * c0
                   + g_hpart[1][(size_t)s*DE + tid] * c1) * invL;
    g_e[(size_t)s*DE + tid] += h;

    float part = h * h;
    #pragma unroll
    for (int off = 16; off; off >>= 1) part += __shfl_xor_sync(0xffffffffu, part, off);
    __shared__ float red[8];
    __shared__ float sc[2];
    if ((tid & 31) == 0) red[tid >> 5] = part;
    __syncthreads();
    if (tid == 0) {
        float S_in = red[0]+red[1]+red[2]+red[3]+red[4]+red[5]+red[6]+red[7];
        float E = g_E[s], P = g_P[s], Gv = g_G[s], l = g_l[s];
        float PE = P * E;
        float P_new = fmaxf(P + (alpha[layer]*S_in - beta[layer]*PE) * DTs, 0.f);
        float E_new = fmaxf(E + (basal[layer] - gamma[layer]*PE) * DTs, 0.f);
        float m_t = 1.f / (1.f + expf(-(E_new - P_new)));
        Gv += (0.1f*E_new - 0.5f*P_new) * DTs;
        float ldec = 0.01f + 0.5f*fmaxf(P_new - 2.f, 0.f);
        float l_new = fminf(fmaxf(l - ldec*DTs, 0.f), 1.f);
        g_E[s] = E_new; g_P[s] = P_new; g_G[s] = Gv; g_l[s] = l_new;
        sc[0] = m_t; sc[1] = l_new;
    }
    __syncthreads();
    if (tid < DM) {
        float mo = g_m[s*DM + tid];
        float mn = 0.9f*mo + 0.1f*sc[0];
        g_m[s*DM + tid]  = mn;
        g_mt[s*DM + tid] = sc[1] * mn;
    }
}

/* -------------------------------------------------------- final output */
__global__ void output_kernel(const float* __restrict__ cin, float* __restrict__ out)
{
    const int s = blockIdx.x, tid = threadIdx.x;
    const float l = g_l[s];
    const bool alive = (l > 0.05f);
    const float af = alive ? 1.f : 0.f;
    out[(size_t)s*DE + tid] = g_e[(size_t)s*DE + tid] * af;
    if (tid < DM) {
        out[M_OFF + s*DM + tid] = g_m[s*DM + tid] * af;
        out[C_OFF + s*DM + tid] = cin[s*DM + tid] * af;
    }
    if (tid == 0) {
        out[E_OFF + s] = g_E[s] * af;
        out[P_OFF + s] = g_P[s] * af;
        out[G_OFF + s] = g_G[s] * af;
        out[L_OFF + s] = l * af;
        out[A_OFF + s] = af;
        if (alive) atomicAdd(&g_alive_count, 1);
    }
}

__global__ void died_kernel(float* __restrict__ out)
{
    out[D_OFF] = (float)(S_TOK - g_alive_count);
}

/* -------------------------------------------------------------- launch */
extern "C" void kernel_launch(void* const* d_in, const int* in_sizes, int n_in,
                              void* d_out, int out_size)
{
    const float* e     = (const float*)d_in[0];
    const float* Ein   = (const float*)d_in[1];
    const float* Pin   = (const float*)d_in[2];
    const float* Gin   = (const float*)d_in[3];
    const float* m     = (const float*)d_in[4];
    const float* c     = (const float*)d_in[5];
    const float* l     = (const float*)d_in[6];
    const float* wq    = (const float*)d_in[7];
    const float* bq    = (const float*)d_in[8];
    const float* wk    = (const float*)d_in[9];
    const float* bk    = (const float*)d_in[10];
    const float* wv    = (const float*)d_in[11];
    const float* bv    = (const float*)d_in[12];
    const float* alpha = (const float*)d_in[13];
    const float* beta  = (const float*)d_in[14];
    const float* gamma = (const float*)d_in[15];
    const float* basal = (const float*)d_in[16];
    float* out = (float*)d_out;

    cudaFuncSetAttribute(attn_kernel, cudaFuncAttributeMaxDynamicSharedMemorySize,
                         ATTN_SMEM_BYTES);

    init_kernel<<<S_TOK*DE/256, 256>>>(e, Ein, Pin, Gin, m, l);
    for (int layer = 0; layer < DEPTH; layer++) {
        qkv_kernel<<<dim3(S_TOK/64, DE/64, 3), 256>>>(c, wq, bq, wk, bk, wv, bv, layer);
        attn_kernel<<<dim3(S_TOK/64, KSPLIT), 256, ATTN_SMEM_BYTES>>>();
        combine_kernel<<<S_TOK, 256>>>(alpha, beta, gamma, basal, layer);
    }
    output_kernel<<<S_TOK, 256>>>(c, out);
    died_kernel<<<1, 1>>>(out);
}

// round 2
// speedup vs baseline: 1.0025x; 1.0025x over previous
#include <cuda_runtime.h>
#include <math.h>

#define S_TOK 4096
#define DE 256
#define DC 64
#define DIN 320
#define DM 64
#define DEPTH 4
#define DTs 0.1f
#define SCALE 0.0625f   /* 1/sqrt(256) */
#define KSPLIT 2

/* output layout offsets (flattened concat of the reference tuple, float32) */
#define E_OFF  (S_TOK*DE)            /* 1048576 */
#define P_OFF  (E_OFF + S_TOK)
#define G_OFF  (P_OFF + S_TOK)
#define M_OFF  (G_OFF + S_TOK)       /* 1060864 */
#define C_OFF  (M_OFF + S_TOK*DM)    /* 1323008 */
#define L_OFF  (C_OFF + S_TOK*DM)    /* 1585152 */
#define A_OFF  (L_OFF + S_TOK)       /* 1589248 */
#define D_OFF  (A_OFF + S_TOK)       /* 1593344 */

/* persistent state (device globals: no allocation allowed) */
__device__ float g_e[S_TOK*DE];
__device__ float g_q[S_TOK*DE];
__device__ float g_k[S_TOK*DE];
__device__ float g_v[S_TOK*DE];
__device__ float g_m[S_TOK*DM];      /* raw m */
__device__ float g_mt[S_TOK*DM];     /* m~ = l*m (combined membrane*lifespan mask) */
__device__ float g_E[S_TOK];
__device__ float g_P[S_TOK];
__device__ float g_G[S_TOK];
__device__ float g_l[S_TOK];
__device__ float g_hpart[KSPLIT][S_TOK*DE];
__device__ float g_Mpart[KSPLIT][S_TOK];
__device__ float g_Lpart[KSPLIT][S_TOK];
__device__ int   g_alive_count;

/* ------------------------------------------------------------------ init */
__global__ void init_kernel(const float* __restrict__ e, const float* __restrict__ Ein,
                            const float* __restrict__ Pin, const float* __restrict__ Gin,
                            const float* __restrict__ min_, const float* __restrict__ lin)
{
    int i = blockIdx.x * 256 + threadIdx.x;      /* grid covers S_TOK*DE exactly */
    g_e[i] = e[i];
    if (i < S_TOK*DM) {
        float mv = min_[i];
        g_m[i]  = mv;
        g_mt[i] = mv * lin[i / DM];
    }
    if (i < S_TOK) {
        g_l[i] = lin[i]; g_E[i] = Ein[i]; g_P[i] = Pin[i]; g_G[i] = Gin[i];
    }
    if (i == 0) g_alive_count = 0;
}

/* ------------------------------------------------------- QKV projections */
/* out = [e|c] @ W + b ; M=4096 K=320 N=256 ; block 64x64, 256 thr, 4x4 micro */
__global__ void __launch_bounds__(256) qkv_kernel(
    const float* __restrict__ cin,
    const float* __restrict__ wq, const float* __restrict__ bq,
    const float* __restrict__ wk, const float* __restrict__ bk,
    const float* __restrict__ wv, const float* __restrict__ bv, int layer)
{
    __shared__ float sA[16][68];   /* x tile transposed [k][m], padded */
    __shared__ float sB[16][64];   /* W tile [k][n] */
    const int tid = threadIdx.x;
    const int m0 = blockIdx.x * 64, n0 = blockIdx.y * 64;
    const int which = blockIdx.z;
    const float* W = (which == 0 ? wq : which == 1 ? wk : wv) + (size_t)layer * DIN * DE;
    const float* B = (which == 0 ? bq : which == 1 ? bk : bv) + layer * DE;
    float* out = (which == 0 ? g_q : which == 1 ? g_k : g_v);
    const int ty = tid >> 4, tx = tid & 15;

    float acc[4][4] = {};
    for (int kt = 0; kt < 20; kt++) {
        const int k0 = kt * 16;
        __syncthreads();
        for (int idx = tid; idx < 1024; idx += 256) {
            int mm = idx >> 4, kk = idx & 15;
            float v;
            if (k0 < 256) v = g_e[(m0 + mm) * DE + k0 + kk];
            else          v = cin[(m0 + mm) * DC + (k0 - 256) + kk];
            sA[kk][mm] = v;
        }
        for (int idx = tid; idx < 1024; idx += 256) {
            int kk = idx >> 6, nn = idx & 63;
            sB[kk][nn] = W[(size_t)(k0 + kk) * DE + n0 + nn];
        }
        __syncthreads();
        #pragma unroll
        for (int kk = 0; kk < 16; kk++) {
            float4 a = *(const float4*)&sA[kk][4 * ty];
            float4 b = *(const float4*)&sB[kk][4 * tx];
            acc[0][0] += a.x*b.x; acc[0][1] += a.x*b.y; acc[0][2] += a.x*b.z; acc[0][3] += a.x*b.w;
            acc[1][0] += a.y*b.x; acc[1][1] += a.y*b.y; acc[1][2] += a.y*b.z; acc[1][3] += a.y*b.w;
            acc[2][0] += a.z*b.x; acc[2][1] += a.z*b.y; acc[2][2] += a.z*b.z; acc[2][3] += a.z*b.w;
            acc[3][0] += a.w*b.x; acc[3][1] += a.w*b.y; acc[3][2] += a.w*b.z; acc[3][3] += a.w*b.w;
        }
    }
    #pragma unroll
    for (int i = 0; i < 4; i++) {
        float4 r;
        r.x = acc[i][0] + B[n0 + 4*tx + 0];
        r.y = acc[i][1] + B[n0 + 4*tx + 1];
        r.z = acc[i][2] + B[n0 + 4*tx + 2];
        r.w = acc[i][3] + B[n0 + 4*tx + 3];
        *(float4*)(out + (size_t)(m0 + 4*ty + i) * DE + n0 + 4*tx) = r;
    }
}

/* ----------------------------------------------------- fused attention */
/* BM=64 queries x (S/KSPLIT) keys, online softmax, unnormalized partials. */
#define ATTN_SMEM_FLOATS (64*260 + 64*260 + 64*128 + 64*68 + 64*68 + 64*64)
#define ATTN_SMEM_BYTES  (ATTN_SMEM_FLOATS * 4)

__global__ void __launch_bounds__(256, 1) attn_kernel()
{
    extern __shared__ float sm[];
    float* sQ  = sm;                 /* [64][260] q tile, row-major padded   */
    float* sK  = sQ  + 64*260;       /* [64][260] k tile                     */
    float* sV  = sK  + 64*260;       /* [64][128] v half-tile                */
    float* sMq = sV  + 64*128;       /* [64][68]  m~ query tile              */
    float* sMk = sMq + 64*68;        /* [64][68]  m~ key tile                */
    float* sP  = sMk + 64*68;        /* [64][64]  scores / probabilities     */

    const int tid  = threadIdx.x;
    const int row0 = blockIdx.x * 64;
    const int ks   = blockIdx.y;
    const int key_base = ks * (S_TOK / KSPLIT);
    const int g = tid >> 5, lane = tid & 31;
    const int ty = tid >> 4, tx = tid & 15;

    for (int idx = tid; idx < 64*64; idx += 256) {
        int r = idx >> 6, d4 = (idx & 63) << 2;
        *(float4*)(sQ + r*260 + d4) = *(const float4*)(g_q + (size_t)(row0 + r)*DE + d4);
    }
    for (int idx = tid; idx < 64*16; idx += 256) {
        int r = idx >> 4, d4 = (idx & 15) << 2;
        *(float4*)(sMq + r*68 + d4) = *(const float4*)(g_mt + (size_t)(row0 + r)*DM + d4);
    }

    float acc[8][8];
    #pragma unroll
    for (int i = 0; i < 8; i++)
        #pragma unroll
        for (int j = 0; j < 8; j++) acc[i][j] = 0.f;
    float rowM[8], rowL[8];
    #pragma unroll
    for (int i = 0; i < 8; i++) { rowM[i] = -INFINITY; rowL[i] = 0.f; }

    for (int kt = 0; kt < (S_TOK / KSPLIT) / 64; kt++) {
        const int key0 = key_base + kt * 64;
        __syncthreads();
        for (int idx = tid; idx < 64*64; idx += 256) {
            int r = idx >> 6, d4 = (idx & 63) << 2;
            *(float4*)(sK + r*260 + d4) = *(const float4*)(g_k + (size_t)(key0 + r)*DE + d4);
        }
        for (int idx = tid; idx < 64*16; idx += 256) {
            int r = idx >> 4, d4 = (idx & 15) << 2;
            *(float4*)(sMk + r*68 + d4) = *(const float4*)(g_mt + (size_t)(key0 + r)*DM + d4);
        }
        for (int idx = tid; idx < 64*32; idx += 256) {
            int r = idx >> 5, d4 = (idx & 31) << 2;
            *(float4*)(sV + r*128 + d4) = *(const float4*)(g_v + (size_t)(key0 + r)*DE + d4);
        }
        __syncthreads();

        /* score phase: q.k over 256 dims, m~.m~ over 64 dims */
        float sqk[4][4] = {}; float smm[4][4] = {};
        {
            const float* qp = sQ + 4*ty*260;
            #pragma unroll 4
            for (int d = 0; d < DE; d += 4) {
                float4 qa[4], kb[4];
                #pragma unroll
                for (int i = 0; i < 4; i++) qa[i] = *(const float4*)(qp + i*260 + d);
                #pragma unroll
                for (int j = 0; j < 4; j++) kb[j] = *(const float4*)(sK + (tx + 16*j)*260 + d);
                #pragma unroll
                for (int i = 0; i < 4; i++)
                    #pragma unroll
                    for (int j = 0; j < 4; j++)
                        sqk[i][j] += qa[i].x*kb[j].x + qa[i].y*kb[j].y
                                   + qa[i].z*kb[j].z + qa[i].w*kb[j].w;
            }
            const float* mp = sMq + 4*ty*68;
            #pragma unroll 4
            for (int d = 0; d < DM; d += 4) {
                float4 qa[4], kb[4];
                #pragma unroll
                for (int i = 0; i < 4; i++) qa[i] = *(const float4*)(mp + i*68 + d);
                #pragma unroll
                for (int j = 0; j < 4; j++) kb[j] = *(const float4*)(sMk + (tx + 16*j)*68 + d);
                #pragma unroll
                for (int i = 0; i < 4; i++)
                    #pragma unroll
                    for (int j = 0; j < 4; j++)
                        smm[i][j] += qa[i].x*kb[j].x + qa[i].y*kb[j].y
                                   + qa[i].z*kb[j].z + qa[i].w*kb[j].w;
            }
        }
        #pragma unroll
        for (int i = 0; i < 4; i++)
            #pragma unroll
            for (int j = 0; j < 4; j++)
                sP[(4*ty + i)*64 + tx + 16*j] = sqk[i][j] * SCALE * smm[i][j];
        __syncthreads();

        /* online softmax: warp g owns rows 8g..8g+7 */
        #pragma unroll
        for (int i = 0; i < 8; i++) {
            const int r = 8*g + i;
            float s0 = sP[r*64 + lane];
            float s1 = sP[r*64 + 32 + lane];
            float tmax = fmaxf(s0, s1);
            #pragma unroll
            for (int off = 16; off; off >>= 1)
                tmax = fmaxf(tmax, __shfl_xor_sync(0xffffffffu, tmax, off));
            float newM = fmaxf(rowM[i], tmax);
            float p0 = __expf(s0 - newM);
            float p1 = __expf(s1 - newM);
            float corr = __expf(rowM[i] - newM);
            float ts = p0 + p1;
            #pragma unroll
            for (int off = 16; off; off >>= 1)
                ts += __shfl_xor_sync(0xffffffffu, ts, off);
            rowL[i] = rowL[i] * corr + ts;
            rowM[i] = newM;
            sP[r*64 + lane] = p0;
            sP[r*64 + 32 + lane] = p1;
            #pragma unroll
            for (int jj = 0; jj < 8; jj++) acc[i][jj] *= corr;
        }
        /* no sync needed: each warp reads only its own sP rows below */

        /* AV half 0 (cols 0..127) */
        #pragma unroll 2
        for (int t = 0; t < 64; t += 4) {
            float4 pv[8];
            #pragma unroll
            for (int i = 0; i < 8; i++) pv[i] = *(const float4*)(sP + (8*g + i)*64 + t);
            #pragma unroll
            for (int tt = 0; tt < 4; tt++) {
                float4 vv = *(const float4*)(sV + (t + tt)*128 + 4*lane);
                #pragma unroll
                for (int i = 0; i < 8; i++) {
                    float p = (tt == 0) ? pv[i].x : (tt == 1) ? pv[i].y : (tt == 2) ? pv[i].z : pv[i].w;
                    acc[i][0] += p*vv.x; acc[i][1] += p*vv.y;
                    acc[i][2] += p*vv.z; acc[i][3] += p*vv.w;
                }
            }
        }
        __syncthreads();
        for (int idx = tid; idx < 64*32; idx += 256) {
            int r = idx >> 5, d4 = (idx & 31) << 2;
            *(float4*)(sV + r*128 + d4) = *(const float4*)(g_v + (size_t)(key0 + r)*DE + 128 + d4);
        }
        __syncthreads();
        /* AV half 1 (cols 128..255) */
        #pragma unroll 2
        for (int t = 0; t < 64; t += 4) {
            float4 pv[8];
            #pragma unroll
            for (int i = 0; i < 8; i++) pv[i] = *(const float4*)(sP + (8*g + i)*64 + t);
            #pragma unroll
            for (int tt = 0; tt < 4; tt++) {
                float4 vv = *(const float4*)(sV + (t + tt)*128 + 4*lane);
                #pragma unroll
                for (int i = 0; i < 8; i++) {
                    float p = (tt == 0) ? pv[i].x : (tt == 1) ? pv[i].y : (tt == 2) ? pv[i].z : pv[i].w;
                    acc[i][4] += p*vv.x; acc[i][5] += p*vv.y;
                    acc[i][6] += p*vv.z; acc[i][7] += p*vv.w;
                }
            }
        }
    }

    /* write unnormalized partials + (M, L) */
    #pragma unroll
    for (int i = 0; i < 8; i++) {
        const int row = row0 + 8*g + i;
        float* hp = &g_hpart[ks][(size_t)row * DE];
        *(float4*)(hp + 4*lane)       = make_float4(acc[i][0], acc[i][1], acc[i][2], acc[i][3]);
        *(float4*)(hp + 128 + 4*lane) = make_float4(acc[i][4], acc[i][5], acc[i][6], acc[i][7]);
    }
    #pragma unroll
    for (int i = 0; i < 8; i++) {
        if (lane == i) {
            g_Mpart[ks][row0 + 8*g + i] = rowM[i];
            g_Lpart[ks][row0 + 8*g + i] = rowL[i];
        }
    }
}

/* ----------------------------------------- combine splits + ODE update */
__global__ void combine_kernel(const float* __restrict__ alpha, const float* __restrict__ beta,
                               const float* __restrict__ gamma, const float* __restrict__ basal,
                               int layer)
{
    const int s = blockIdx.x, tid = threadIdx.x;
    const float M0 = g_Mpart[0][s], M1 = g_Mpart[1][s];
    const float L0 = g_Lpart[0][s], L1 = g_Lpart[1][s];
    const float M  = fmaxf(M0, M1);
    const float c0 = __expf(M0 - M), c1 = __expf(M1 - M);
    const float invL = 1.0f / (L0 * c0 + L1 * c1);
    const float h = (g_hpart[0][(size_t)s*DE + tid] * c0
                   + g_hpart[1][(size_t)s*DE + tid] * c1) * invL;
    g_e[(size_t)s*DE + tid] += h;

    float part = h * h;
    #pragma unroll
    for (int off = 16; off; off >>= 1) part += __shfl_xor_sync(0xffffffffu, part, off);
    __shared__ float red[8];
    __shared__ float sc[2];
    if ((tid & 31) == 0) red[tid >> 5] = part;
    __syncthreads();
    if (tid == 0) {
        float S_in = red[0]+red[1]+red[2]+red[3]+red[4]+red[5]+red[6]+red[7];
        float E = g_E[s], P = g_P[s], Gv = g_G[s], l = g_l[s];
        float PE = P * E;
        float P_new = fmaxf(P + (alpha[layer]*S_in - beta[layer]*PE) * DTs, 0.f);
        float E_new = fmaxf(E + (basal[layer] - gamma[layer]*PE) * DTs, 0.f);
        float m_t = 1.f / (1.f + expf(-(E_new - P_new)));
        Gv += (0.1f*E_new - 0.5f*P_new) * DTs;
        float ldec = 0.01f + 0.5f*fmaxf(P_new - 2.f, 0.f);
        float l_new = fminf(fmaxf(l - ldec*DTs, 0.f), 1.f);
        g_E[s] = E_new; g_P[s] = P_new; g_G[s] = Gv; g_l[s] = l_new;
        sc[0] = m_t; sc[1] = l_new;
    }
    __syncthreads();
    if (tid < DM) {
        float mo = g_m[s*DM + tid];
        float mn = 0.9f*mo + 0.1f*sc[0];
        g_m[s*DM + tid]  = mn;
        g_mt[s*DM + tid] = sc[1] * mn;
    }
}

/* -------------------------------------------------------- final output */
__global__ void output_kernel(const float* __restrict__ cin, float* __restrict__ out)
{
    const int s = blockIdx.x, tid = threadIdx.x;
    const float l = g_l[s];
    const bool alive = (l > 0.05f);
    const float af = alive ? 1.f : 0.f;
    out[(size_t)s*DE + tid] = g_e[(size_t)s*DE + tid] * af;
    if (tid < DM) {
        out[M_OFF + s*DM + tid] = g_m[s*DM + tid] * af;
        out[C_OFF + s*DM + tid] = cin[s*DM + tid] * af;
    }
    if (tid == 0) {
        out[E_OFF + s] = g_E[s] * af;
        out[P_OFF + s] = g_P[s] * af;
        out[G_OFF + s] = g_G[s] * af;
        out[L_OFF + s] = l * af;
        out[A_OFF + s] = af;
        if (alive) atomicAdd(&g_alive_count, 1);
    }
}

__global__ void died_kernel(float* __restrict__ out)
{
    out[D_OFF] = (float)(S_TOK - g_alive_count);
}

/* -------------------------------------------------------------- launch */
extern "C" void kernel_launch(void* const* d_in, const int* in_sizes, int n_in,
                              void* d_out, int out_size)
{
    const float* e     = (const float*)d_in[0];
    const float* Ein   = (const float*)d_in[1];
    const float* Pin   = (const float*)d_in[2];
    const float* Gin   = (const float*)d_in[3];
    const float* m     = (const float*)d_in[4];
    const float* c     = (const float*)d_in[5];
    const float* l     = (const float*)d_in[6];
    const float* wq    = (const float*)d_in[7];
    const float* bq    = (const float*)d_in[8];
    const float* wk    = (const float*)d_in[9];
    const float* bk    = (const float*)d_in[10];
    const float* wv    = (const float*)d_in[11];
    const float* bv    = (const float*)d_in[12];
    const float* alpha = (const float*)d_in[13];
    const float* beta  = (const float*)d_in[14];
    const float* gamma = (const float*)d_in[15];
    const float* basal = (const float*)d_in[16];
    float* out = (float*)d_out;

    cudaFuncSetAttribute(attn_kernel, cudaFuncAttributeMaxDynamicSharedMemorySize,
                         ATTN_SMEM_BYTES);

    init_kernel<<<S_TOK*DE/256, 256>>>(e, Ein, Pin, Gin, m, l);
    for (int layer = 0; layer < DEPTH; layer++) {
        qkv_kernel<<<dim3(S_TOK/64, DE/64, 3), 256>>>(c, wq, bq, wk, bk, wv, bv, layer);
        attn_kernel<<<dim3(S_TOK/64, KSPLIT), 256, ATTN_SMEM_BYTES>>>();
        combine_kernel<<<S_TOK, 256>>>(alpha, beta, gamma, basal, layer);
    }
    output_kernel<<<S_TOK, 256>>>(c, out);
    died_kernel<<<1, 1>>>(out);
}